// round 3
// baseline (speedup 1.0000x reference)
#include <cuda_runtime.h>
#include <math.h>

#define BATCH 2
#define SEQ   4096
#define EMB   512
#define DQ    64
#define NC    129          // number of window diagonals
#define ZCONST 3967.0f     // 4096 - 129 zero-columns contributing exp(0)=1

// ---- scratch (allocation-free: device globals) ----
__device__ float g_Q[BATCH * SEQ * DQ];        // 2 MB
__device__ float g_K[BATCH * SEQ * DQ];        // 2 MB
__device__ float g_Vc[BATCH * NC * DQ];        // V rows 0..128
__device__ float g_Vtail[BATCH * DQ];          // sum of V rows 129..4095
__device__ float g_part[BATCH * 32 * EMB];     // xsum partials

// ============================================================
// Kernel 1: Q and K projections. 64 rows per block.
// thread: d = t&63, row-group rg = t>>6 handles 16 rows.
// ============================================================
__global__ void proj_qk_kernel(const float* __restrict__ x,
                               const float* __restrict__ Wq, const float* __restrict__ bq,
                               const float* __restrict__ Wk, const float* __restrict__ bk) {
    const int b  = blockIdx.y;
    const int n0 = blockIdx.x * 64;
    const int t  = threadIdx.x;
    const int d  = t & 63;
    const int rg = t >> 6;

    __shared__ float xs[64][132];   // 128-col chunk, padded

    float qa[16], ka[16];
#pragma unroll
    for (int i = 0; i < 16; i++) { qa[i] = 0.f; ka[i] = 0.f; }

    const float* xb = x + ((size_t)b * SEQ + n0) * EMB;

    for (int k0 = 0; k0 < EMB; k0 += 128) {
        __syncthreads();
        // load 64x128 chunk of x (float4)
        for (int idx = t; idx < 64 * 32; idx += 256) {
            int r = idx >> 5, c4 = idx & 31;
            float4 v = *(const float4*)(xb + (size_t)r * EMB + k0 + c4 * 4);
            xs[r][c4 * 4 + 0] = v.x; xs[r][c4 * 4 + 1] = v.y;
            xs[r][c4 * 4 + 2] = v.z; xs[r][c4 * 4 + 3] = v.w;
        }
        __syncthreads();
#pragma unroll 4
        for (int k = 0; k < 128; k++) {
            float wq = Wq[(size_t)(k0 + k) * DQ + d];
            float wk = Wk[(size_t)(k0 + k) * DQ + d];
#pragma unroll
            for (int i = 0; i < 16; i++) {
                float xv = xs[rg * 16 + i][k];
                qa[i] = fmaf(xv, wq, qa[i]);
                ka[i] = fmaf(xv, wk, ka[i]);
            }
        }
    }
    float bqv = bq[d], bkv = bk[d];
#pragma unroll
    for (int i = 0; i < 16; i++) {
        int n = n0 + rg * 16 + i;
        g_Q[((size_t)b * SEQ + n) * DQ + d] = qa[i] + bqv;
        g_K[((size_t)b * SEQ + n) * DQ + d] = ka[i] + bkv;
    }
}

// ============================================================
// Kernel 2: V projection, rows 0..128 only
// ============================================================
__global__ void proj_vhead_kernel(const float* __restrict__ x,
                                  const float* __restrict__ Wv,
                                  const float* __restrict__ bv) {
    const int b = blockIdx.y, r = blockIdx.x, d = threadIdx.x;   // 64 threads
    __shared__ float xs[EMB];
    const float* xr = x + ((size_t)b * SEQ + r) * EMB;
    for (int i = d; i < EMB / 4; i += 64)
        ((float4*)xs)[i] = ((const float4*)xr)[i];
    __syncthreads();
    float acc = 0.f;
#pragma unroll 8
    for (int k = 0; k < EMB; k++)
        acc = fmaf(xs[k], Wv[(size_t)k * DQ + d], acc);
    g_Vc[(b * NC + r) * DQ + d] = acc + bv[d];
}

// ============================================================
// Kernel 3: partial row-sums of x over rows 129..4095 (deterministic 2-stage)
// ============================================================
__global__ void xsum_partial_kernel(const float* __restrict__ x) {
    const int b = blockIdx.y, ci = blockIdx.x, t = threadIdx.x;  // 256 threads
    int r0 = 129 + ci * 124;
    int r1 = r0 + 124; if (r1 > SEQ) r1 = SEQ;
    const float* xb = x + (size_t)b * SEQ * EMB;
    float s0 = 0.f, s1 = 0.f;
    for (int r = r0; r < r1; r++) {
        s0 += xb[(size_t)r * EMB + t];
        s1 += xb[(size_t)r * EMB + t + 256];
    }
    g_part[(b * 32 + ci) * EMB + t]       = s0;
    g_part[(b * 32 + ci) * EMB + t + 256] = s1;
}

// ============================================================
// Kernel 4: Vtail[b][d] = xsum · Wv[:,d] + 3967*bv[d]
// ============================================================
__global__ void vtail_kernel(const float* __restrict__ Wv, const float* __restrict__ bv) {
    const int b = blockIdx.x, t = threadIdx.x;   // 512 threads
    __shared__ float xsum[EMB];
    float s = 0.f;
#pragma unroll
    for (int ci = 0; ci < 32; ci++) s += g_part[(b * 32 + ci) * EMB + t];
    xsum[t] = s;
    __syncthreads();
    if (t < DQ) {
        float acc = 0.f;
#pragma unroll 8
        for (int k = 0; k < EMB; k++)
            acc = fmaf(xsum[k], Wv[(size_t)k * DQ + t], acc);
        g_Vtail[b * DQ + t] = acc + ZCONST * bv[t];
    }
}

// ============================================================
// Kernel 5: attention core. 64 query rows per block, 256 threads.
//  phase 1: S(64x192) = Q_tile * Ks^T (Ks zero-padded -> invalid scores = 0)
//  phase 1.5: E = exp(S) scattered by c = cc - n'
//  Z: per-row sum + 3967; phase 2: O = E * Vc + Vtail, scaled by 1/Z
// ============================================================
#define KS_PITCH 65
#define ES_PITCH 132
#define SM_KS 0
#define SM_QS (192 * KS_PITCH)
#define SM_ES (SM_QS + 64 * KS_PITCH)
#define SM_VS (SM_ES + 64 * ES_PITCH)
#define SM_ZI (SM_VS + NC * KS_PITCH)
#define SM_VT (SM_ZI + 64)
#define SM_FLOATS (SM_VT + 64)
#define SM_BYTES (SM_FLOATS * 4)

__global__ void attn_kernel(float* __restrict__ out) {
    extern __shared__ float sm[];
    float* Ks = sm + SM_KS;
    float* Qs = sm + SM_QS;
    float* Es = sm + SM_ES;
    float* Vs = sm + SM_VS;
    float* Zi = sm + SM_ZI;
    float* Vt = sm + SM_VT;

    const int b = blockIdx.y, n0 = blockIdx.x * 64, t = threadIdx.x;

    // --- stage K window (192 rows, zero-padded), Q tile, V head, Vtail ---
    const float* Kb = g_K + (size_t)b * SEQ * DQ;
    for (int idx = t; idx < 192 * 16; idx += 256) {
        int r = idx >> 4, c4 = idx & 15;
        int j = n0 - 64 + r;
        float4 v = (j >= 0 && j < SEQ) ? *(const float4*)(Kb + (size_t)j * DQ + c4 * 4)
                                       : make_float4(0.f, 0.f, 0.f, 0.f);
        Ks[r * KS_PITCH + c4 * 4 + 0] = v.x; Ks[r * KS_PITCH + c4 * 4 + 1] = v.y;
        Ks[r * KS_PITCH + c4 * 4 + 2] = v.z; Ks[r * KS_PITCH + c4 * 4 + 3] = v.w;
    }
    const float* Qb = g_Q + ((size_t)b * SEQ + n0) * DQ;
    for (int idx = t; idx < 64 * 16; idx += 256) {
        int r = idx >> 4, c4 = idx & 15;
        float4 v = *(const float4*)(Qb + (size_t)r * DQ + c4 * 4);
        Qs[r * KS_PITCH + c4 * 4 + 0] = v.x; Qs[r * KS_PITCH + c4 * 4 + 1] = v.y;
        Qs[r * KS_PITCH + c4 * 4 + 2] = v.z; Qs[r * KS_PITCH + c4 * 4 + 3] = v.w;
    }
    for (int idx = t; idx < NC * 16; idx += 256) {
        int r = idx >> 4, c4 = idx & 15;
        float4 v = *(const float4*)(g_Vc + ((size_t)b * NC + r) * DQ + c4 * 4);
        Vs[r * KS_PITCH + c4 * 4 + 0] = v.x; Vs[r * KS_PITCH + c4 * 4 + 1] = v.y;
        Vs[r * KS_PITCH + c4 * 4 + 2] = v.z; Vs[r * KS_PITCH + c4 * 4 + 3] = v.w;
    }
    if (t < DQ) Vt[t] = g_Vtail[b * DQ + t];
    __syncthreads();

    const int tx = t & 15, ty = t >> 4;

    // --- phase 1: banded score tile 64x192, thread tile 4 rows x 12 cols ---
    float acc[4][12];
#pragma unroll
    for (int i = 0; i < 4; i++)
#pragma unroll
        for (int jj = 0; jj < 12; jj++) acc[i][jj] = 0.f;

#pragma unroll 4
    for (int k = 0; k < DQ; k++) {
        float qv[4], kv[12];
#pragma unroll
        for (int i = 0; i < 4; i++)   qv[i]  = Qs[(ty * 4 + i) * KS_PITCH + k];
#pragma unroll
        for (int jj = 0; jj < 12; jj++) kv[jj] = Ks[(tx + 16 * jj) * KS_PITCH + k];
#pragma unroll
        for (int i = 0; i < 4; i++)
#pragma unroll
            for (int jj = 0; jj < 12; jj++)
                acc[i][jj] = fmaf(qv[i], kv[jj], acc[i][jj]);
    }

    // --- phase 1.5: exp + scatter into Es[row][c], c = cc - n' ---
#pragma unroll
    for (int i = 0; i < 4; i++) {
        int np = ty * 4 + i;
#pragma unroll
        for (int jj = 0; jj < 12; jj++) {
            int cc = tx + 16 * jj;
            int c = cc - np;
            if (c >= 0 && c < NC)
                Es[np * ES_PITCH + c] = expf(acc[i][jj]);
        }
    }
    __syncthreads();

    // --- Z per row: 8 warps x 8 rows ---
    {
        const int w = t >> 5, lane = t & 31;
        for (int rr = 0; rr < 8; rr++) {
            int r = w * 8 + rr;
            float s = Es[r * ES_PITCH + lane] + Es[r * ES_PITCH + lane + 32]
                    + Es[r * ES_PITCH + lane + 64] + Es[r * ES_PITCH + lane + 96];
            if (lane == 0) s += Es[r * ES_PITCH + 128];
#pragma unroll
            for (int o = 16; o > 0; o >>= 1) s += __shfl_xor_sync(0xffffffffu, s, o);
            if (lane == 0) Zi[r] = 1.0f / (s + ZCONST);
        }
    }
    __syncthreads();

    // --- phase 2: O(64x64) = E(64x129) * Vs(129x64), thread tile 4x4 ---
    float oacc[4][4];
#pragma unroll
    for (int i = 0; i < 4; i++)
#pragma unroll
        for (int i2 = 0; i2 < 4; i2++) oacc[i][i2] = 0.f;

#pragma unroll 3
    for (int c = 0; c < NC; c++) {
        float ev[4], vv[4];
#pragma unroll
        for (int i = 0; i < 4; i++)  ev[i]  = Es[(ty * 4 + i) * ES_PITCH + c];
#pragma unroll
        for (int i2 = 0; i2 < 4; i2++) vv[i2] = Vs[c * KS_PITCH + tx + 16 * i2];
#pragma unroll
        for (int i = 0; i < 4; i++)
#pragma unroll
            for (int i2 = 0; i2 < 4; i2++)
                oacc[i][i2] = fmaf(ev[i], vv[i2], oacc[i][i2]);
    }

#pragma unroll
    for (int i = 0; i < 4; i++) {
        int np = ty * 4 + i;
        float zi = Zi[np];
#pragma unroll
        for (int i2 = 0; i2 < 4; i2++) {
            int d = tx + 16 * i2;
            out[((size_t)b * SEQ + n0 + np) * DQ + d] = (oacc[i][i2] + Vt[d]) * zi;
        }
    }
}

// ============================================================
// launcher
// ============================================================
extern "C" void kernel_launch(void* const* d_in, const int* in_sizes, int n_in,
                              void* d_out, int out_size) {
    const float* x  = (const float*)d_in[0];
    const float* Wq = (const float*)d_in[1];
    const float* bq = (const float*)d_in[2];
    const float* Wk = (const float*)d_in[3];
    const float* bk = (const float*)d_in[4];
    const float* Wv = (const float*)d_in[5];
    const float* bv = (const float*)d_in[6];
    float* out = (float*)d_out;

    cudaFuncSetAttribute(attn_kernel, cudaFuncAttributeMaxDynamicSharedMemorySize, SM_BYTES);

    proj_qk_kernel<<<dim3(SEQ / 64, BATCH), 256>>>(x, Wq, bq, Wk, bk);
    proj_vhead_kernel<<<dim3(NC, BATCH), 64>>>(x, Wv, bv);
    xsum_partial_kernel<<<dim3(32, BATCH), 256>>>(x);
    vtail_kernel<<<BATCH, 512>>>(Wv, bv);
    attn_kernel<<<dim3(SEQ / 64, BATCH), 256, SM_BYTES>>>(out);
}

// round 4
// speedup vs baseline: 1.4201x; 1.4201x over previous
#include <cuda_runtime.h>
#include <math.h>

#define BATCH 2
#define SEQ   4096
#define EMB   512
#define DQ    64
#define NC    129          // number of window diagonals
#define ZCONST 3967.0f     // 4096 - 129 zero-columns contributing exp(0)=1

// ---- scratch (allocation-free: device globals) ----
__device__ float g_Q[BATCH * SEQ * DQ];        // 2 MB
__device__ float g_K[BATCH * SEQ * DQ];        // 2 MB
__device__ float g_Vc[BATCH * NC * DQ];        // V rows 0..128
__device__ float g_Vtail[BATCH * DQ];          // sum of V rows 129..4095
__device__ float g_part[BATCH * 32 * EMB];     // xsum partials

// packed fp32x2 FMA (Blackwell FFMA2): acc = a*b + acc elementwise on 2 floats
__device__ __forceinline__ void ffma2(unsigned long long& acc,
                                      unsigned long long a,
                                      unsigned long long b) {
    asm("fma.rn.f32x2 %0, %1, %2, %0;" : "+l"(acc) : "l"(a), "l"(b));
}

// ============================================================
// Kernel 1: Q and K projections, FFMA2 k-pair formulation.
// 64 rows per block, 256 threads: d = t&63, rg = t>>6 (16 rows each).
// smem: xs[64][130] row-major (k contiguous),
//       wqs/wks[64][130] transposed (k contiguous per d).
// ============================================================
#define XS_PITCH 130
#define PQ_XS  0
#define PQ_WQ  (64 * XS_PITCH)
#define PQ_WK  (2 * 64 * XS_PITCH)
#define PQ_FLOATS (3 * 64 * XS_PITCH)
#define PQ_BYTES (PQ_FLOATS * 4)

__global__ void __launch_bounds__(256, 1)
proj_qk_kernel(const float* __restrict__ x,
               const float* __restrict__ Wq, const float* __restrict__ bq,
               const float* __restrict__ Wk, const float* __restrict__ bk) {
    extern __shared__ float sm[];
    float* xs  = sm + PQ_XS;
    float* wqs = sm + PQ_WQ;
    float* wks = sm + PQ_WK;

    const int b  = blockIdx.y;
    const int n0 = blockIdx.x * 64;
    const int t  = threadIdx.x;
    const int d  = t & 63;
    const int rg = t >> 6;

    unsigned long long qa[16], ka[16];
#pragma unroll
    for (int i = 0; i < 16; i++) { qa[i] = 0ull; ka[i] = 0ull; }

    const float* xb = x + ((size_t)b * SEQ + n0) * EMB;

    for (int k0 = 0; k0 < EMB; k0 += 128) {
        __syncthreads();
        // stage 64x128 chunk of x, row-major (k contiguous)
        for (int idx = t; idx < 64 * 32; idx += 256) {
            int r = idx >> 5, c4 = idx & 31;
            float4 v = *(const float4*)(xb + (size_t)r * EMB + k0 + c4 * 4);
            float* p = xs + r * XS_PITCH + c4 * 4;
            p[0] = v.x; p[1] = v.y; p[2] = v.z; p[3] = v.w;
        }
        // stage W chunks transposed: wqs[d][kk]
        for (int idx = t; idx < 128 * 16; idx += 256) {
            int kk = idx >> 4, c4 = idx & 15;
            float4 q4 = *(const float4*)(Wq + (size_t)(k0 + kk) * DQ + c4 * 4);
            float4 k4 = *(const float4*)(Wk + (size_t)(k0 + kk) * DQ + c4 * 4);
            wqs[(c4 * 4 + 0) * XS_PITCH + kk] = q4.x;
            wqs[(c4 * 4 + 1) * XS_PITCH + kk] = q4.y;
            wqs[(c4 * 4 + 2) * XS_PITCH + kk] = q4.z;
            wqs[(c4 * 4 + 3) * XS_PITCH + kk] = q4.w;
            wks[(c4 * 4 + 0) * XS_PITCH + kk] = k4.x;
            wks[(c4 * 4 + 1) * XS_PITCH + kk] = k4.y;
            wks[(c4 * 4 + 2) * XS_PITCH + kk] = k4.z;
            wks[(c4 * 4 + 3) * XS_PITCH + kk] = k4.w;
        }
        __syncthreads();

        const unsigned long long* wq2 = (const unsigned long long*)(wqs + d * XS_PITCH);
        const unsigned long long* wk2 = (const unsigned long long*)(wks + d * XS_PITCH);
        const float* xrow0 = xs + (rg * 16) * XS_PITCH;

#pragma unroll 4
        for (int kp = 0; kp < 64; kp++) {      // k-pairs within the 128-chunk
            unsigned long long w2q = wq2[kp];
            unsigned long long w2k = wk2[kp];
#pragma unroll
            for (int i = 0; i < 16; i++) {
                unsigned long long x2 =
                    *(const unsigned long long*)(xrow0 + i * XS_PITCH + kp * 2);
                ffma2(qa[i], x2, w2q);
                ffma2(ka[i], x2, w2k);
            }
        }
    }

    float bqv = bq[d], bkv = bk[d];
#pragma unroll
    for (int i = 0; i < 16; i++) {
        int n = n0 + rg * 16 + i;
        float qlo = __uint_as_float((unsigned)qa[i]);
        float qhi = __uint_as_float((unsigned)(qa[i] >> 32));
        float klo = __uint_as_float((unsigned)ka[i]);
        float khi = __uint_as_float((unsigned)(ka[i] >> 32));
        g_Q[((size_t)b * SEQ + n) * DQ + d] = qlo + qhi + bqv;
        g_K[((size_t)b * SEQ + n) * DQ + d] = klo + khi + bkv;
    }
}

// ============================================================
// Kernel 2: V projection, rows 0..128 only. 128 threads, split-k.
// ============================================================
__global__ void proj_vhead_kernel(const float* __restrict__ x,
                                  const float* __restrict__ Wv,
                                  const float* __restrict__ bv) {
    const int b = blockIdx.y, r = blockIdx.x, t = threadIdx.x;  // 128 threads
    __shared__ float xsh[EMB];
    __shared__ float red[2][DQ];
    const float* xr = x + ((size_t)b * SEQ + r) * EMB;
    ((float4*)xsh)[t] = ((const float4*)xr)[t];   // 128 * 16B = 2KB
    __syncthreads();
    const int d = t & 63, h = t >> 6;
    float acc = 0.f;
    const int kb = h * 256;
#pragma unroll 8
    for (int k = 0; k < 256; k++)
        acc = fmaf(xsh[kb + k], Wv[(size_t)(kb + k) * DQ + d], acc);
    red[h][d] = acc;
    __syncthreads();
    if (t < DQ)
        g_Vc[(b * NC + r) * DQ + t] = red[0][t] + red[1][t] + bv[t];
}

// ============================================================
// Kernel 3: partial row-sums of x over rows 129..4095 (float4)
// ============================================================
__global__ void xsum_partial_kernel(const float* __restrict__ x) {
    const int b = blockIdx.y, ci = blockIdx.x, t = threadIdx.x;  // 128 threads
    int r0 = 129 + ci * 124;
    int r1 = r0 + 124; if (r1 > SEQ) r1 = SEQ;
    const float* xb = x + (size_t)b * SEQ * EMB;
    float4 s = make_float4(0.f, 0.f, 0.f, 0.f);
#pragma unroll 4
    for (int r = r0; r < r1; r++) {
        float4 v = *(const float4*)(xb + (size_t)r * EMB + t * 4);
        s.x += v.x; s.y += v.y; s.z += v.z; s.w += v.w;
    }
    *(float4*)(g_part + (b * 32 + ci) * EMB + t * 4) = s;
}

// ============================================================
// Kernel 4: Vtail[b][d] = xsum . Wv[:,d] + 3967*bv[d]  (parallel)
// ============================================================
__global__ void vtail_kernel(const float* __restrict__ Wv, const float* __restrict__ bv) {
    const int b = blockIdx.x, t = threadIdx.x;   // 512 threads
    __shared__ float xsum[EMB];
    __shared__ float p2[8][DQ];
    float s = 0.f;
#pragma unroll
    for (int ci = 0; ci < 32; ci++) s += g_part[(b * 32 + ci) * EMB + t];
    xsum[t] = s;
    __syncthreads();
    const int g = t >> 6, d = t & 63;        // 8 k-groups x 64 d
    float acc = 0.f;
    const int kb = g * 64;
#pragma unroll 16
    for (int kk = 0; kk < 64; kk++)
        acc = fmaf(xsum[kb + kk], Wv[(size_t)(kb + kk) * DQ + d], acc);
    p2[g][d] = acc;
    __syncthreads();
    if (t < DQ) {
        float tot = 0.f;
#pragma unroll
        for (int g2 = 0; g2 < 8; g2++) tot += p2[g2][t];
        g_Vtail[b * DQ + t] = tot + ZCONST * bv[t];
    }
}

// ============================================================
// Kernel 5: attention core (unchanged from passing R0 version)
// ============================================================
#define KS_PITCH 65
#define ES_PITCH 132
#define SM_KS 0
#define SM_QS (192 * KS_PITCH)
#define SM_ES (SM_QS + 64 * KS_PITCH)
#define SM_VS (SM_ES + 64 * ES_PITCH)
#define SM_ZI (SM_VS + NC * KS_PITCH)
#define SM_VT (SM_ZI + 64)
#define SM_FLOATS (SM_VT + 64)
#define SM_BYTES (SM_FLOATS * 4)

__global__ void attn_kernel(float* __restrict__ out) {
    extern __shared__ float sm[];
    float* Ks = sm + SM_KS;
    float* Qs = sm + SM_QS;
    float* Es = sm + SM_ES;
    float* Vs = sm + SM_VS;
    float* Zi = sm + SM_ZI;
    float* Vt = sm + SM_VT;

    const int b = blockIdx.y, n0 = blockIdx.x * 64, t = threadIdx.x;

    const float* Kb = g_K + (size_t)b * SEQ * DQ;
    for (int idx = t; idx < 192 * 16; idx += 256) {
        int r = idx >> 4, c4 = idx & 15;
        int j = n0 - 64 + r;
        float4 v = (j >= 0 && j < SEQ) ? *(const float4*)(Kb + (size_t)j * DQ + c4 * 4)
                                       : make_float4(0.f, 0.f, 0.f, 0.f);
        Ks[r * KS_PITCH + c4 * 4 + 0] = v.x; Ks[r * KS_PITCH + c4 * 4 + 1] = v.y;
        Ks[r * KS_PITCH + c4 * 4 + 2] = v.z; Ks[r * KS_PITCH + c4 * 4 + 3] = v.w;
    }
    const float* Qb = g_Q + ((size_t)b * SEQ + n0) * DQ;
    for (int idx = t; idx < 64 * 16; idx += 256) {
        int r = idx >> 4, c4 = idx & 15;
        float4 v = *(const float4*)(Qb + (size_t)r * DQ + c4 * 4);
        Qs[r * KS_PITCH + c4 * 4 + 0] = v.x; Qs[r * KS_PITCH + c4 * 4 + 1] = v.y;
        Qs[r * KS_PITCH + c4 * 4 + 2] = v.z; Qs[r * KS_PITCH + c4 * 4 + 3] = v.w;
    }
    for (int idx = t; idx < NC * 16; idx += 256) {
        int r = idx >> 4, c4 = idx & 15;
        float4 v = *(const float4*)(g_Vc + ((size_t)b * NC + r) * DQ + c4 * 4);
        Vs[r * KS_PITCH + c4 * 4 + 0] = v.x; Vs[r * KS_PITCH + c4 * 4 + 1] = v.y;
        Vs[r * KS_PITCH + c4 * 4 + 2] = v.z; Vs[r * KS_PITCH + c4 * 4 + 3] = v.w;
    }
    if (t < DQ) Vt[t] = g_Vtail[b * DQ + t];
    __syncthreads();

    const int tx = t & 15, ty = t >> 4;

    float acc[4][12];
#pragma unroll
    for (int i = 0; i < 4; i++)
#pragma unroll
        for (int jj = 0; jj < 12; jj++) acc[i][jj] = 0.f;

#pragma unroll 4
    for (int k = 0; k < DQ; k++) {
        float qv[4], kv[12];
#pragma unroll
        for (int i = 0; i < 4; i++)   qv[i]  = Qs[(ty * 4 + i) * KS_PITCH + k];
#pragma unroll
        for (int jj = 0; jj < 12; jj++) kv[jj] = Ks[(tx + 16 * jj) * KS_PITCH + k];
#pragma unroll
        for (int i = 0; i < 4; i++)
#pragma unroll
            for (int jj = 0; jj < 12; jj++)
                acc[i][jj] = fmaf(qv[i], kv[jj], acc[i][jj]);
    }

#pragma unroll
    for (int i = 0; i < 4; i++) {
        int np = ty * 4 + i;
#pragma unroll
        for (int jj = 0; jj < 12; jj++) {
            int cc = tx + 16 * jj;
            int c = cc - np;
            if (c >= 0 && c < NC)
                Es[np * ES_PITCH + c] = expf(acc[i][jj]);
        }
    }
    __syncthreads();

    {
        const int w = t >> 5, lane = t & 31;
        for (int rr = 0; rr < 8; rr++) {
            int r = w * 8 + rr;
            float s = Es[r * ES_PITCH + lane] + Es[r * ES_PITCH + lane + 32]
                    + Es[r * ES_PITCH + lane + 64] + Es[r * ES_PITCH + lane + 96];
            if (lane == 0) s += Es[r * ES_PITCH + 128];
#pragma unroll
            for (int o = 16; o > 0; o >>= 1) s += __shfl_xor_sync(0xffffffffu, s, o);
            if (lane == 0) Zi[r] = 1.0f / (s + ZCONST);
        }
    }
    __syncthreads();

    float oacc[4][4];
#pragma unroll
    for (int i = 0; i < 4; i++)
#pragma unroll
        for (int i2 = 0; i2 < 4; i2++) oacc[i][i2] = 0.f;

#pragma unroll 3
    for (int c = 0; c < NC; c++) {
        float ev[4], vv[4];
#pragma unroll
        for (int i = 0; i < 4; i++)  ev[i]  = Es[(ty * 4 + i) * ES_PITCH + c];
#pragma unroll
        for (int i2 = 0; i2 < 4; i2++) vv[i2] = Vs[c * KS_PITCH + tx + 16 * i2];
#pragma unroll
        for (int i = 0; i < 4; i++)
#pragma unroll
            for (int i2 = 0; i2 < 4; i2++)
                oacc[i][i2] = fmaf(ev[i], vv[i2], oacc[i][i2]);
    }

#pragma unroll
    for (int i = 0; i < 4; i++) {
        int np = ty * 4 + i;
        float zi = Zi[np];
#pragma unroll
        for (int i2 = 0; i2 < 4; i2++) {
            int d = tx + 16 * i2;
            out[((size_t)b * SEQ + n0 + np) * DQ + d] = (oacc[i][i2] + Vt[d]) * zi;
        }
    }
}

// ============================================================
// launcher
// ============================================================
extern "C" void kernel_launch(void* const* d_in, const int* in_sizes, int n_in,
                              void* d_out, int out_size) {
    const float* x  = (const float*)d_in[0];
    const float* Wq = (const float*)d_in[1];
    const float* bq = (const float*)d_in[2];
    const float* Wk = (const float*)d_in[3];
    const float* bk = (const float*)d_in[4];
    const float* Wv = (const float*)d_in[5];
    const float* bv = (const float*)d_in[6];
    float* out = (float*)d_out;

    cudaFuncSetAttribute(proj_qk_kernel, cudaFuncAttributeMaxDynamicSharedMemorySize, PQ_BYTES);
    cudaFuncSetAttribute(attn_kernel,    cudaFuncAttributeMaxDynamicSharedMemorySize, SM_BYTES);

    proj_qk_kernel<<<dim3(SEQ / 64, BATCH), 256, PQ_BYTES>>>(x, Wq, bq, Wk, bk);
    proj_vhead_kernel<<<dim3(NC, BATCH), 128>>>(x, Wv, bv);
    xsum_partial_kernel<<<dim3(32, BATCH), 128>>>(x);
    vtail_kernel<<<BATCH, 512>>>(Wv, bv);
    attn_kernel<<<dim3(SEQ / 64, BATCH), 256, SM_BYTES>>>(out);
}